// round 3
// baseline (speedup 1.0000x reference)
#include <cuda_runtime.h>

// CASSI forward gather, 4 outputs/thread for MLP.
//
// y[m, c] = sum_{l=0..63} x[m, c-l, l] * ca[m, c-l]   (0 <= c-l < N)
//
// Each thread owns 4 consecutive output columns c..c+3 -> 4 independent
// load/accumulate streams. Rotation l = (c+i+j)&63 keeps warp addresses
// consecutive (the 4 streams jointly cover 128 contiguous floats per step).
// Out-of-range n handled branch-free: x address clamped, s_ca halo zeroed.

#define MM   1024
#define NN   1024
#define LL   64
#define OUTC (NN + LL - 1)          // 1087
#define T    128                    // threads per block
#define OPT  4                      // outputs per thread
#define BC   (T * OPT)              // 512 output columns per block
#define CAW  (BC + LL - 1)          // 575 staged ca values

__global__ __launch_bounds__(T)
void cassi_gather4_kernel(const float* __restrict__ x,
                          const float* __restrict__ ca,
                          float* __restrict__ y)
{
    __shared__ float s_ca[CAW];

    const int m      = blockIdx.y;
    const int c_base = blockIdx.x * BC;
    const int tid    = threadIdx.x;
    const int nbase  = c_base - (LL - 1);

    // Stage ca with zeroed halo (covers all n this block can touch).
    #pragma unroll
    for (int i = tid; i < CAW; i += T) {
        const int n = nbase + i;
        s_ca[i] = ((unsigned)n < NN) ? ca[m * NN + n] : 0.0f;
    }
    __syncthreads();

    const int c = c_base + tid * OPT;       // first of 4 owned columns
    if (c >= OUTC) return;

    const float* xrow = x + (size_t)m * (NN * LL);

    float acc0 = 0.f, acc1 = 0.f, acc2 = 0.f, acc3 = 0.f;

    #pragma unroll 8
    for (int j = 0; j < LL; ++j) {
        // stream i: l = (c+i+j)&63, n = c+i-l, addr = n*64 + l
        const int l0 = (c + 0 + j) & (LL - 1);
        const int l1 = (c + 1 + j) & (LL - 1);
        const int l2 = (c + 2 + j) & (LL - 1);
        const int l3 = (c + 3 + j) & (LL - 1);
        const int n0 = c + 0 - l0;
        const int n1 = c + 1 - l1;
        const int n2 = c + 2 - l2;
        const int n3 = c + 3 - l3;
        // clamp address; s_ca halo is 0 for out-of-range n -> product is 0
        const int a0 = max(0, min(NN - 1, n0)) * LL + l0;
        const int a1 = max(0, min(NN - 1, n1)) * LL + l1;
        const int a2 = max(0, min(NN - 1, n2)) * LL + l2;
        const int a3 = max(0, min(NN - 1, n3)) * LL + l3;
        acc0 = fmaf(xrow[a0], s_ca[n0 - nbase], acc0);
        acc1 = fmaf(xrow[a1], s_ca[n1 - nbase], acc1);
        acc2 = fmaf(xrow[a2], s_ca[n2 - nbase], acc2);
        acc3 = fmaf(xrow[a3], s_ca[n3 - nbase], acc3);
    }

    float* yrow = y + (size_t)m * OUTC;
    if (c + 0 < OUTC) yrow[c + 0] = acc0;
    if (c + 1 < OUTC) yrow[c + 1] = acc1;
    if (c + 2 < OUTC) yrow[c + 2] = acc2;
    if (c + 3 < OUTC) yrow[c + 3] = acc3;
}

extern "C" void kernel_launch(void* const* d_in, const int* in_sizes, int n_in,
                              void* d_out, int out_size)
{
    const float* x  = (const float*)d_in[0];
    const float* ca = (const float*)d_in[1];
    float* y        = (float*)d_out;

    dim3 grid((OUTC + BC - 1) / BC, MM);    // (3, 1024)
    cassi_gather4_kernel<<<grid, T>>>(x, ca, y);
}

// round 4
// speedup vs baseline: 1.5178x; 1.5178x over previous
#include <cuda_runtime.h>

// CASSI forward, warp-level n-sweep gather.
//
// y[m, c] = sum_{n=c-63}^{c} x[m, n, c-n] * ca[m, n]
//
// Each warp owns 32 consecutive outputs c0..c0+31. Iterating the source row
// n = (warp_c0 - 63) + t for t = 0..95, lane k (output c = warp_c0+k) reads
// x[n][c-n]: addresses are 32 CONSECUTIVE floats per step (no wrap, ever),
// and step-to-step the address advances by exactly +63 floats (affine).
// ca[n] is lane-uniform -> free LDS broadcast. Lane activity: l = k+63-t
// must lie in [0,64); 33 of 96 steps are fully active, the rest predicated.

#define MM   1024
#define NN   1024
#define LL   64
#define OUTC (NN + LL - 1)   // 1087
#define T    256             // threads per block
#define NSTEP (32 + LL * 2 - 2 + 2)  // not used; steps = 32 + 64 = 96

__global__ __launch_bounds__(T)
void cassi_nsweep_kernel(const float* __restrict__ x,
                         const float* __restrict__ ca,
                         float* __restrict__ y)
{
    __shared__ float s_ca[T + LL - 1];   // n in [c0-63, c0+T-1]

    const int m     = blockIdx.y;
    const int c0    = blockIdx.x * T;
    const int tid   = threadIdx.x;
    const int nbase = c0 - (LL - 1);

    #pragma unroll
    for (int i = tid; i < T + LL - 1; i += T) {
        const int n = nbase + i;
        s_ca[i] = ((unsigned)n < NN) ? ca[m * NN + n] : 0.0f;
    }
    __syncthreads();

    const int k   = tid & 31;            // lane
    const int w32 = tid & ~31;           // warp base within block
    const int c   = c0 + tid;            // owned output column

    const float* xrow = x + (size_t)m * (NN * LL);
    float acc = 0.0f;

    if (c0 >= (LL - 1) && (c0 + T - 1) < NN) {
        // Interior blocks: every accessed n is in [0, NN). Affine pointer:
        // step t reads element (n = c0+w32-63+t, l = k+63-t)
        //   = xrow[(c0+w32-63)*64 + (k+63) + 63*t]
        const float* xp = xrow + (size_t)(c0 + w32 - (LL - 1)) * LL + (k + LL - 1);
        #pragma unroll
        for (int t = 0; t < 32 + 2 * (LL - 1) + 1 - 31; ++t) {  // 96 steps
            const int l = k + (LL - 1) - t;
            if ((unsigned)l < LL)
                acc = fmaf(xp[t * (LL - 1)], s_ca[w32 + t], acc);
        }
    } else {
        // Edge blocks: also guard n.
        #pragma unroll
        for (int t = 0; t < 96; ++t) {
            const int l = k + (LL - 1) - t;
            const int n = c0 + w32 - (LL - 1) + t;
            if ((unsigned)l < LL && (unsigned)n < NN)
                acc = fmaf(xrow[(size_t)n * LL + l], s_ca[w32 + t], acc);
        }
    }

    if (c < OUTC)
        y[(size_t)m * OUTC + c] = acc;
}

extern "C" void kernel_launch(void* const* d_in, const int* in_sizes, int n_in,
                              void* d_out, int out_size)
{
    const float* x  = (const float*)d_in[0];
    const float* ca = (const float*)d_in[1];
    float* y        = (float*)d_out;

    dim3 grid((OUTC + T - 1) / T, MM);   // (5, 1024)
    cassi_nsweep_kernel<<<grid, T>>>(x, ca, y);
}

// round 5
// speedup vs baseline: 1.6209x; 1.0680x over previous
#include <cuda_runtime.h>

// CASSI forward gather, R1 rotation pattern x 4 independent m-streams.
//
// y[m, c] = sum_{l=0..63} x[m, c-l, l] * ca[m, c-l]
//
// Rotation l=(c+j)&63 keeps each warp-LDG over 32 consecutive floats.
// Each thread computes the same column c for 4 consecutive m rows:
// 4 independent accumulate streams sharing one address computation
// (m-stride = 64K floats = constant immediate offsets) -> 4x bytes in
// flight per warp at unchanged coalescing.

#define MM   1024
#define NN   1024
#define LL   64
#define OUTC (NN + LL - 1)   // 1087
#define T    256             // threads per block
#define MB   4               // m rows per thread
#define MSTR (NN * LL)       // 65536 floats between m planes

__global__ __launch_bounds__(T, 4)
void cassi_gather_m4_kernel(const float* __restrict__ x,
                            const float* __restrict__ ca,
                            float* __restrict__ y)
{
    __shared__ float s_ca[MB][T + LL - 1];

    const int m0    = blockIdx.y * MB;
    const int c0    = blockIdx.x * T;
    const int tid   = threadIdx.x;
    const int nbase = c0 - (LL - 1);

    for (int i = tid; i < T + LL - 1; i += T) {
        const int n = nbase + i;
        const bool ok = ((unsigned)n < NN);
        #pragma unroll
        for (int mm = 0; mm < MB; ++mm)
            s_ca[mm][i] = ok ? ca[(m0 + mm) * NN + n] : 0.0f;
    }
    __syncthreads();

    const int c      = c0 + tid;
    const int lstart = c & (LL - 1);
    const float* x0  = x + (size_t)m0 * MSTR;

    float acc0 = 0.f, acc1 = 0.f, acc2 = 0.f, acc3 = 0.f;

    if (c0 >= (LL - 1) && (c0 + T - 1) <= (NN - 1)) {
        // Interior: every n = c - l in range, no predicates.
        #pragma unroll
        for (int j = 0; j < LL; ++j) {
            const int l   = (lstart + j) & (LL - 1);
            const int n   = c - l;
            const int idx = n * LL + l;
            const int si  = n - nbase;
            acc0 = fmaf(x0[idx + 0 * MSTR], s_ca[0][si], acc0);
            acc1 = fmaf(x0[idx + 1 * MSTR], s_ca[1][si], acc1);
            acc2 = fmaf(x0[idx + 2 * MSTR], s_ca[2][si], acc2);
            acc3 = fmaf(x0[idx + 3 * MSTR], s_ca[3][si], acc3);
        }
    } else {
        // Edge c-tiles: clamp address, s_ca halo is zero for OOB n.
        #pragma unroll
        for (int j = 0; j < LL; ++j) {
            const int l   = (lstart + j) & (LL - 1);
            const int n   = c - l;
            const int nc  = max(0, min(NN - 1, n));
            const int idx = nc * LL + l;
            const int si  = n - nbase;
            acc0 = fmaf(x0[idx + 0 * MSTR], s_ca[0][si], acc0);
            acc1 = fmaf(x0[idx + 1 * MSTR], s_ca[1][si], acc1);
            acc2 = fmaf(x0[idx + 2 * MSTR], s_ca[2][si], acc2);
            acc3 = fmaf(x0[idx + 3 * MSTR], s_ca[3][si], acc3);
        }
    }

    if (c < OUTC) {
        y[(size_t)(m0 + 0) * OUTC + c] = acc0;
        y[(size_t)(m0 + 1) * OUTC + c] = acc1;
        y[(size_t)(m0 + 2) * OUTC + c] = acc2;
        y[(size_t)(m0 + 3) * OUTC + c] = acc3;
    }
}

extern "C" void kernel_launch(void* const* d_in, const int* in_sizes, int n_in,
                              void* d_out, int out_size)
{
    const float* x  = (const float*)d_in[0];
    const float* ca = (const float*)d_in[1];
    float* y        = (float*)d_out;

    dim3 grid((OUTC + T - 1) / T, MM / MB);   // (5, 256)
    cassi_gather_m4_kernel<<<grid, T>>>(x, ca, y);
}